// round 12
// baseline (speedup 1.0000x reference)
#include <cuda_runtime.h>
#include <cstdint>
#include <math.h>

// Problem constants
#define D   784
#define H   500
#define HP  512
#define B   512
#define S   28           // segments (784 = 28*28)
#define L   28           // steps per segment
#define BD  (B*D)
#define CHS 7            // steps per chunk in k_scan
#define NCH 4            // chunks (4*7 = 28)
#define TPB 512          // k_scan threads (16 warps)

typedef unsigned long long u64;
typedef unsigned int u32;

// Static device scratch
__device__ float g_WT[D*HP];     // W^T padded: [d][h]
__device__ float g_Vp[D*HP];     // V padded:   [d][h]
__device__ float g_c [HP];
__device__ float g_A [B*S*HP];   // partials then checkpoints: [b][s][h]

// ---- packed f32x2 helpers -------------------------------------------------
__device__ __forceinline__ u64 ffma2(u64 a, u64 b, u64 c) {
    u64 d;
    asm("fma.rn.f32x2 %0, %1, %2, %3;" : "=l"(d) : "l"(a), "l"(b), "l"(c));
    return d;
}
__device__ __forceinline__ u64 add2(u64 a, u64 b) {
    u64 d;
    asm("add.rn.f32x2 %0, %1, %2;" : "=l"(d) : "l"(a), "l"(b));
    return d;
}
__device__ __forceinline__ u64 relu2(u64 a) {
    u64 r;
    asm("{\n\t.reg .f32 lo, hi;\n\t"
        "mov.b64 {lo, hi}, %1;\n\t"
        "max.f32 lo, lo, 0f00000000;\n\t"
        "max.f32 hi, hi, 0f00000000;\n\t"
        "mov.b64 %0, {lo, hi};\n\t}" : "=l"(r) : "l"(a));
    return r;
}
__device__ __forceinline__ u64 pack2(float x) {
    u64 r;
    asm("mov.b64 %0, {%1, %1};" : "=l"(r) : "f"(x));
    return r;
}
__device__ __forceinline__ float hadd2(u64 a) {
    float lo, hi;
    asm("mov.b64 {%0, %1}, %2;" : "=f"(lo), "=f"(hi) : "l"(a));
    return lo + hi;
}
__device__ __forceinline__ u32 s2u(const void* p) {
    u32 a;
    asm("{ .reg .u64 t; cvta.to.shared.u64 t, %1; cvt.u32.u64 %0, t; }"
        : "=r"(a) : "l"(p));
    return a;
}
__device__ __forceinline__ void cp_async16(u32 dst, const float* src) {
    asm volatile("cp.async.cg.shared.global [%0], [%1], 16;"
                 :: "r"(dst), "l"(src));
}

// ---------------------------------------------------------------------------
// K0: fused pack. gridDim.x = 784+25 blocks.
//   blocks [0,784): pad V row d -> g_Vp[d][:], plus c on d==0 (512 thr)
//   blocks [784, 784+25): transpose W 32-col strip (256 thr used as 32x8)
// ---------------------------------------------------------------------------
__global__ void k_pack(const float* __restrict__ V,
                       const float* __restrict__ c,
                       const float* __restrict__ W) {
    if (blockIdx.x < D) {
        int d = blockIdx.x;
        int t = threadIdx.x;
        g_Vp[d*HP + t] = (t < H) ? V[d*H + t] : 0.0f;
        if (d == 0) g_c[t] = (t < H) ? c[t] : 0.0f;
        return;
    }
    // W transpose: strip of 32 d-columns, loop over h in 32-row tiles.
    __shared__ float tile[32][33];
    int d0 = (blockIdx.x - D) * 32;
    int tx = threadIdx.x & 31;
    int ty = (threadIdx.x >> 5) & 7;       // use first 256 threads as 32x8
    if (threadIdx.x >= 256) return;
    for (int h0 = 0; h0 < HP; h0 += 32) {
        #pragma unroll
        for (int i = 0; i < 4; i++) {
            int h = h0 + ty + 8*i;
            int d = d0 + tx;
            float v = 0.0f;
            if (h < H && d < D) v = W[h*D + d];
            tile[ty + 8*i][tx] = v;
        }
        __syncthreads();
        #pragma unroll
        for (int i = 0; i < 4; i++) {
            int d = d0 + ty + 8*i;
            int h = h0 + tx;
            if (d < D) g_WT[d*HP + h] = tile[tx][ty + 8*i];
        }
        __syncthreads();
    }
}

// ---------------------------------------------------------------------------
// K1: partial GEMM. P_s[rows,:] = X[rows, sL:(s+1)L] @ W[sL:(s+1)L, :]
//     Stored at g_A[row][s][:]  (layout [b][s][h]).
// ---------------------------------------------------------------------------
__global__ __launch_bounds__(256)
void k_partial(const float* __restrict__ x) {
    int s  = blockIdx.x;         // 0..26
    int rb = blockIdx.y;         // 0..15
    int t  = threadIdx.x;        // h-pair index
    int rowbase = rb * 32;

    __shared__ u64 sxp[32 * L];
    for (int i = t; i < 32 * L; i += 256) {
        int r = i / L, j = i - r * L;
        sxp[i] = pack2(x[(rowbase + r)*D + s*L + j]);
    }
    __syncthreads();

    u64 acc[32];
    #pragma unroll
    for (int r = 0; r < 32; r++) acc[r] = 0ull;

    const u64* W1 = (const u64*)g_WT;
    #pragma unroll 2
    for (int j = 0; j < L; j++) {
        u64 wv = W1[(size_t)(s*L + j)*256 + t];
        #pragma unroll
        for (int r = 0; r < 32; r++)
            acc[r] = ffma2(sxp[r*L + j], wv, acc[r]);
    }

    u64* A1 = (u64*)g_A;
    #pragma unroll
    for (int r = 0; r < 32; r++)
        A1[((size_t)(rowbase + r)*S + s)*256 + t] = acc[r];
}

// ---------------------------------------------------------------------------
// K2: prefix over segments, one thread per (b,h), in place, MLP=28.
// ---------------------------------------------------------------------------
__global__ __launch_bounds__(256)
void k_prefix() {
    int g = blockIdx.x * 256 + threadIdx.x;
    int h = g & (HP - 1);
    int b = g >> 9;
    float* base = g_A + (size_t)b*S*HP + h;
    float p[S];
    #pragma unroll
    for (int s = 0; s < S; s++) p[s] = base[s*HP];
    float v = g_c[h];
    #pragma unroll
    for (int s = 0; s < S; s++) {
        float t = p[s];
        base[s*HP] = v;
        v += t;
    }
}

// ---------------------------------------------------------------------------
// K3: scan (identical to round 11), 16 warps, lane=row, cp.async dbl-buffer.
// ---------------------------------------------------------------------------
#define SMEM_SCAN_BYTES (21596*4)

__global__ __launch_bounds__(TPB, 2)
void k_scan(const float* __restrict__ x,
            const float* __restrict__ u,
            const float* __restrict__ bvec,
            float* __restrict__ out) {
    extern __shared__ __align__(16) float smem[];
    float* svw  = smem;                 // 2*7168
    float* part = svw + 2*7168;         // 3584
    float* sx   = part + 3584;          // 928
    float* su   = sx + 928;             // 928
    float* sb   = su + 928;             // 28
    float* sl   = sb + 28;              // 896
    float* sxs  = sl + 896;             // 896

    int s    = blockIdx.x;       // 0..27
    int rb   = blockIdx.y;       // 0..15
    int tid  = threadIdx.x;
    int w    = tid >> 5;         // 0..15
    int lane = tid & 31;
    int rowbase = rb * 32;

    // Chunk-0 prefetch. f = jj*256 + w2*16 + which*8 + q (float4 units),
    // layout [jj][w2][V 32 | W 32].
    {
        int dbase = s*L;
        #pragma unroll
        for (int k = 0; k < 4; k++) {
            int f = tid + k*TPB;
            if (f < 1792) {
                int q = f & 7;
                int gg = f >> 3;
                int which = gg & 1;
                int gw = gg >> 1;
                int w2 = gw & 15;
                int jj = gw >> 4;
                const float* src = (which ? g_WT : g_Vp)
                                 + (size_t)(dbase + jj)*HP + w2*32 + q*4;
                cp_async16(s2u(svw) + (u32)(f*16), src);
            }
        }
        asm volatile("cp.async.commit_group;");
    }

    // State init: lane = row, slice [32w, 32w+32).
    u64 a[16];
    {
        const ulonglong2* A2 = (const ulonglong2*)
            (g_A + ((size_t)(rowbase + lane)*S + s)*HP + w*32);
        #pragma unroll
        for (int i = 0; i < 8; i++) {
            ulonglong2 q = A2[i];
            a[2*i] = q.x; a[2*i+1] = q.y;
        }
    }

    // Stage x, u (stride-29 rows) and b.
    for (int i = tid; i < 32*L; i += TPB) {
        int r = i / L, j = i - r*L;
        size_t g = (size_t)(rowbase + r)*D + s*L + j;
        sx[r*29 + j] = x[g];
        su[r*29 + j] = u[g];
    }
    if (tid < L) sb[tid] = bvec[s*L + tid];

    asm volatile("cp.async.wait_group 0;");
    __syncthreads();

    for (int c = 0; c < NCH; c++) {
        float* buf = svw + (c & 1)*7168;

        if (c < NCH-1) {
            float* nbuf = svw + ((c+1) & 1)*7168;
            int dbase = s*L + (c+1)*CHS;
            #pragma unroll
            for (int k = 0; k < 4; k++) {
                int f = tid + k*TPB;
                if (f < 1792) {
                    int q = f & 7;
                    int gg = f >> 3;
                    int which = gg & 1;
                    int gw = gg >> 1;
                    int w2 = gw & 15;
                    int jj = gw >> 4;
                    const float* src = (which ? g_WT : g_Vp)
                                     + (size_t)(dbase + jj)*HP + w2*32 + q*4;
                    cp_async16(s2u(nbuf) + (u32)(f*16), src);
                }
            }
            asm volatile("cp.async.commit_group;");
        }

        #pragma unroll 1
        for (int jj = 0; jj < CHS; jj++) {
            int j = c*CHS + jj;
            u64 xx = pack2(sx[lane*29 + j]);
            const ulonglong2* Vb = (const ulonglong2*)(buf + (jj*16 + w)*64);
            const ulonglong2* Wb = Vb + 8;   // +32 floats
            u64 dp0 = 0ull, dp1 = 0ull;
            #pragma unroll
            for (int i = 0; i < 8; i++) {
                ulonglong2 vq = Vb[i];
                ulonglong2 wq = Wb[i];
                dp0 = ffma2(relu2(a[2*i  ]), vq.x, dp0);
                dp1 = ffma2(relu2(a[2*i+1]), vq.y, dp1);
                a[2*i  ] = ffma2(xx, wq.x, a[2*i  ]);
                a[2*i+1] = ffma2(xx, wq.y, a[2*i+1]);
            }
            part[(jj*16 + w)*32 + lane] = hadd2(add2(dp0, dp1));
        }

        __syncthreads();   // part complete; buf fully consumed

        if (tid < 32*CHS) {
            int row = tid & 31, jj = tid >> 5;
            float sum = 0.0f;
            #pragma unroll
            for (int w2 = 0; w2 < 16; w2++)
                sum += part[(jj*16 + w2)*32 + row];
            int j = c*CHS + jj;
            float lv = sum + sb[j];
            float uu = su[row*29 + j];
            float e  = expf(-lv);
            float xs = (fmaf(uu, e, uu) < 1.0f) ? 1.0f : 0.0f;
            sl [row*L + j] = lv;
            sxs[row*L + j] = xs;
        }

        asm volatile("cp.async.wait_group 0;");
        __syncthreads();   // part free; next buffer visible
    }

    for (int i = tid; i < 32*L; i += TPB) {
        int r = i / L, j = i - r*L;
        size_t g = (size_t)(rowbase + r)*D + s*L + j;
        out[g]      = sl[i];
        out[BD + g] = sxs[i];
    }
}

// ---------------------------------------------------------------------------
// Inputs: x[B,D], u[B,D], W[H,D], c[H], V[D,H], b[D]
// Output: [ l (B*D) | x_sample (B*D) ]
// Launch order chosen so k_scan is launch index 3 (the ncu-captured slot).
// ---------------------------------------------------------------------------
extern "C" void kernel_launch(void* const* d_in, const int* in_sizes, int n_in,
                              void* d_out, int out_size) {
    (void)in_sizes; (void)n_in; (void)out_size;
    const float* x    = (const float*)d_in[0];
    const float* u    = (const float*)d_in[1];
    const float* W    = (const float*)d_in[2];
    const float* c    = (const float*)d_in[3];
    const float* V    = (const float*)d_in[4];
    const float* bvec = (const float*)d_in[5];
    float* out = (float*)d_out;

    cudaFuncSetAttribute(k_scan, cudaFuncAttributeMaxDynamicSharedMemorySize,
                         SMEM_SCAN_BYTES);

    k_pack   <<<D + (D+31)/32, HP>>>(V, c, W);      // launch 0
    k_partial<<<dim3(S-1, B/32), 256>>>(x);          // launch 1
    k_prefix <<<(B*HP)/256, 256>>>();                // launch 2
    k_scan   <<<dim3(S, B/32), TPB, SMEM_SCAN_BYTES>>>(x, u, bvec, out);  // launch 3
}

// round 15
// speedup vs baseline: 1.0051x; 1.0051x over previous
#include <cuda_runtime.h>
#include <cstdint>
#include <math.h>

// Problem constants
#define D   784
#define H   500
#define HP  512
#define B   512
#define S   28           // segments (784 = 28*28)
#define L   28           // steps per segment
#define BD  (B*D)
#define CHS 7            // steps per chunk in k_scan
#define NCH 4            // chunks (4*7 = 28)
#define TPB 512          // k_scan threads (16 warps)

typedef unsigned long long u64;
typedef unsigned int u32;

// Static device scratch
__device__ float g_WT[D*HP];     // W^T padded: [d][h]
__device__ float g_Vp[D*HP];     // V padded:   [d][h]
__device__ float g_c [HP];
__device__ float g_A [B*S*HP];   // partials then checkpoints: [b][s][h]

// ---- packed f32x2 helpers -------------------------------------------------
__device__ __forceinline__ u64 ffma2(u64 a, u64 b, u64 c) {
    u64 d;
    asm("fma.rn.f32x2 %0, %1, %2, %3;" : "=l"(d) : "l"(a), "l"(b), "l"(c));
    return d;
}
__device__ __forceinline__ u64 add2(u64 a, u64 b) {
    u64 d;
    asm("add.rn.f32x2 %0, %1, %2;" : "=l"(d) : "l"(a), "l"(b));
    return d;
}
// relu on a packed pair: 2 scalar max (mov.b64 halves are register renames).
__device__ __forceinline__ u64 relu2(u64 a) {
    u64 r;
    asm("{\n\t.reg .f32 lo, hi;\n\t"
        "mov.b64 {lo, hi}, %1;\n\t"
        "max.f32 lo, lo, 0f00000000;\n\t"
        "max.f32 hi, hi, 0f00000000;\n\t"
        "mov.b64 %0, {lo, hi};\n\t}" : "=l"(r) : "l"(a));
    return r;
}
__device__ __forceinline__ u64 pack2(float x) {
    u64 r;
    asm("mov.b64 %0, {%1, %1};" : "=l"(r) : "f"(x));
    return r;
}
__device__ __forceinline__ float hadd2(u64 a) {
    float lo, hi;
    asm("mov.b64 {%0, %1}, %2;" : "=f"(lo), "=f"(hi) : "l"(a));
    return lo + hi;
}
__device__ __forceinline__ u32 s2u(const void* p) {
    u32 a;
    asm("{ .reg .u64 t; cvta.to.shared.u64 t, %1; cvt.u32.u64 %0, t; }"
        : "=r"(a) : "l"(p));
    return a;
}
__device__ __forceinline__ void cp_async16(u32 dst, const float* src) {
    asm volatile("cp.async.cg.shared.global [%0], [%1], 16;"
                 :: "r"(dst), "l"(src));
}

// ---------------------------------------------------------------------------
// K0: fused pack. gridDim.x = 784+25 blocks, 512 threads.
//   blocks [0,784): pad V row d -> g_Vp[d][:], plus c on d==0
//   blocks [784, 784+25): transpose W 32-col strip (512 thr as 32x16)
// ---------------------------------------------------------------------------
__global__ void k_pack(const float* __restrict__ V,
                       const float* __restrict__ c,
                       const float* __restrict__ W) {
    if (blockIdx.x < D) {
        int d = blockIdx.x;
        int t = threadIdx.x;
        g_Vp[d*HP + t] = (t < H) ? V[d*H + t] : 0.0f;
        if (d == 0) g_c[t] = (t < H) ? c[t] : 0.0f;
        return;
    }
    __shared__ float tile[32][33];
    int d0 = (blockIdx.x - D) * 32;
    int tx = threadIdx.x & 31;
    int ty = threadIdx.x >> 5;             // 0..15
    for (int h0 = 0; h0 < HP; h0 += 32) {
        #pragma unroll
        for (int i = 0; i < 2; i++) {
            int h = h0 + ty + 16*i;
            int d = d0 + tx;
            float v = 0.0f;
            if (h < H && d < D) v = W[h*D + d];
            tile[ty + 16*i][tx] = v;
        }
        __syncthreads();
        #pragma unroll
        for (int i = 0; i < 2; i++) {
            int d = d0 + ty + 16*i;
            int h = h0 + tx;
            if (d < D) g_WT[d*HP + h] = tile[tx][ty + 16*i];
        }
        __syncthreads();
    }
}

// ---------------------------------------------------------------------------
// K1: partial GEMM. P_s[rows,:] = X[rows, sL:(s+1)L] @ W[sL:(s+1)L, :]
//     Stored at g_A[row][s][:]  (layout [b][s][h]).
// ---------------------------------------------------------------------------
__global__ __launch_bounds__(256)
void k_partial(const float* __restrict__ x) {
    int s  = blockIdx.x;         // 0..26
    int rb = blockIdx.y;         // 0..15
    int t  = threadIdx.x;        // h-pair index
    int rowbase = rb * 32;

    __shared__ u64 sxp[32 * L];
    for (int i = t; i < 32 * L; i += 256) {
        int r = i / L, j = i - r * L;
        sxp[i] = pack2(x[(rowbase + r)*D + s*L + j]);
    }
    __syncthreads();

    u64 acc[32];
    #pragma unroll
    for (int r = 0; r < 32; r++) acc[r] = 0ull;

    const u64* W1 = (const u64*)g_WT;
    #pragma unroll 2
    for (int j = 0; j < L; j++) {
        u64 wv = W1[(size_t)(s*L + j)*256 + t];
        #pragma unroll
        for (int r = 0; r < 32; r++)
            acc[r] = ffma2(sxp[r*L + j], wv, acc[r]);
    }

    u64* A1 = (u64*)g_A;
    #pragma unroll
    for (int r = 0; r < 32; r++)
        A1[((size_t)(rowbase + r)*S + s)*256 + t] = acc[r];
}

// ---------------------------------------------------------------------------
// K2: prefix over segments, one thread per (b,h), in place, MLP=28.
// ---------------------------------------------------------------------------
__global__ __launch_bounds__(256)
void k_prefix() {
    int g = blockIdx.x * 256 + threadIdx.x;
    int h = g & (HP - 1);
    int b = g >> 9;
    float* base = g_A + (size_t)b*S*HP + h;
    float p[S];
    #pragma unroll
    for (int s = 0; s < S; s++) p[s] = base[s*HP];
    float v = g_c[h];
    #pragma unroll
    for (int s = 0; s < S; s++) {
        float t = p[s];
        base[s*HP] = v;
        v += t;
    }
}

// ---------------------------------------------------------------------------
// K3: scan, 16 warps, lane=row, cp.async dbl-buffer.
// Fully unrolled chunk loop (immediate LDS offsets); 4 dp chains for ILP.
// ---------------------------------------------------------------------------
#define SMEM_SCAN_BYTES (21596*4)

__global__ __launch_bounds__(TPB, 2)
void k_scan(const float* __restrict__ x,
            const float* __restrict__ u,
            const float* __restrict__ bvec,
            float* __restrict__ out) {
    extern __shared__ __align__(16) float smem[];
    float* svw  = smem;                 // 2*7168
    float* part = svw + 2*7168;         // 3584
    float* sx   = part + 3584;          // 928
    float* su   = sx + 928;             // 928
    float* sb   = su + 928;             // 28
    float* sl   = sb + 28;              // 896
    float* sxs  = sl + 896;             // 896

    int s    = blockIdx.x;       // 0..27
    int rb   = blockIdx.y;       // 0..15
    int tid  = threadIdx.x;
    int w    = tid >> 5;         // 0..15
    int lane = tid & 31;
    int rowbase = rb * 32;

    // Chunk-0 prefetch. f = jj*256 + w2*16 + which*8 + q (float4 units),
    // layout [jj][w2][V 32 | W 32].
    {
        int dbase = s*L;
        #pragma unroll
        for (int k = 0; k < 4; k++) {
            int f = tid + k*TPB;
            if (f < 1792) {
                int q = f & 7;
                int gg = f >> 3;
                int which = gg & 1;
                int gw = gg >> 1;
                int w2 = gw & 15;
                int jj = gw >> 4;
                const float* src = (which ? g_WT : g_Vp)
                                 + (size_t)(dbase + jj)*HP + w2*32 + q*4;
                cp_async16(s2u(svw) + (u32)(f*16), src);
            }
        }
        asm volatile("cp.async.commit_group;");
    }

    // State init: lane = row, slice [32w, 32w+32).
    u64 a[16];
    {
        const ulonglong2* A2 = (const ulonglong2*)
            (g_A + ((size_t)(rowbase + lane)*S + s)*HP + w*32);
        #pragma unroll
        for (int i = 0; i < 8; i++) {
            ulonglong2 q = A2[i];
            a[2*i] = q.x; a[2*i+1] = q.y;
        }
    }

    // Stage x, u (stride-29 rows) and b.
    for (int i = tid; i < 32*L; i += TPB) {
        int r = i / L, j = i - r*L;
        size_t g = (size_t)(rowbase + r)*D + s*L + j;
        sx[r*29 + j] = x[g];
        su[r*29 + j] = u[g];
    }
    if (tid < L) sb[tid] = bvec[s*L + tid];

    asm volatile("cp.async.wait_group 0;");
    __syncthreads();

    for (int c = 0; c < NCH; c++) {
        float* buf = svw + (c & 1)*7168;

        if (c < NCH-1) {
            float* nbuf = svw + ((c+1) & 1)*7168;
            int dbase = s*L + (c+1)*CHS;
            #pragma unroll
            for (int k = 0; k < 4; k++) {
                int f = tid + k*TPB;
                if (f < 1792) {
                    int q = f & 7;
                    int gg = f >> 3;
                    int which = gg & 1;
                    int gw = gg >> 1;
                    int w2 = gw & 15;
                    int jj = gw >> 4;
                    const float* src = (which ? g_WT : g_Vp)
                                     + (size_t)(dbase + jj)*HP + w2*32 + q*4;
                    cp_async16(s2u(nbuf) + (u32)(f*16), src);
                }
            }
            asm volatile("cp.async.commit_group;");
        }

        // Compute 7 steps — fully unrolled, 4 independent dp chains.
        // Step stride: 16 warps * 64 floats = 1024 floats = 256 ulonglong2.
        const ulonglong2* base2 = (const ulonglong2*)(buf + w*64);
        const float* sxl = sx + lane*29 + c*CHS;
        #pragma unroll
        for (int jj = 0; jj < CHS; jj++) {
            u64 xx = pack2(sxl[jj]);
            const ulonglong2* Vb = base2 + jj*256;  // 256 u2 = 1024 floats/step
            const ulonglong2* Wb = Vb + 8;          // +32 floats
            u64 dp0 = 0ull, dp1 = 0ull, dp2 = 0ull, dp3 = 0ull;
            #pragma unroll
            for (int i = 0; i < 4; i++) {
                ulonglong2 vq0 = Vb[2*i];
                ulonglong2 vq1 = Vb[2*i+1];
                ulonglong2 wq0 = Wb[2*i];
                ulonglong2 wq1 = Wb[2*i+1];
                dp0 = ffma2(relu2(a[4*i  ]), vq0.x, dp0);
                dp1 = ffma2(relu2(a[4*i+1]), vq0.y, dp1);
                dp2 = ffma2(relu2(a[4*i+2]), vq1.x, dp2);
                dp3 = ffma2(relu2(a[4*i+3]), vq1.y, dp3);
                a[4*i  ] = ffma2(xx, wq0.x, a[4*i  ]);
                a[4*i+1] = ffma2(xx, wq0.y, a[4*i+1]);
                a[4*i+2] = ffma2(xx, wq1.x, a[4*i+2]);
                a[4*i+3] = ffma2(xx, wq1.y, a[4*i+3]);
            }
            part[(jj*16 + w)*32 + lane] =
                hadd2(add2(add2(dp0, dp1), add2(dp2, dp3)));
        }

        __syncthreads();   // part complete; buf fully consumed

        if (tid < 32*CHS) {
            int row = tid & 31, jj = tid >> 5;
            float sum = 0.0f;
            #pragma unroll
            for (int w2 = 0; w2 < 16; w2++)
                sum += part[(jj*16 + w2)*32 + row];
            int j = c*CHS + jj;
            float lv = sum + sb[j];
            float uu = su[row*29 + j];
            float e  = expf(-lv);
            float xs = (fmaf(uu, e, uu) < 1.0f) ? 1.0f : 0.0f;
            sl [row*L + j] = lv;
            sxs[row*L + j] = xs;
        }

        asm volatile("cp.async.wait_group 0;");
        __syncthreads();   // part free; next buffer visible
    }

    for (int i = tid; i < 32*L; i += TPB) {
        int r = i / L, j = i - r*L;
        size_t g = (size_t)(rowbase + r)*D + s*L + j;
        out[g]      = sl[i];
        out[BD + g] = sxs[i];
    }
}

// ---------------------------------------------------------------------------
// Inputs: x[B,D], u[B,D], W[H,D], c[H], V[D,H], b[D]
// Output: [ l (B*D) | x_sample (B*D) ]
// Launch order keeps k_scan at index 3 (the ncu-captured slot).
// ---------------------------------------------------------------------------
extern "C" void kernel_launch(void* const* d_in, const int* in_sizes, int n_in,
                              void* d_out, int out_size) {
    (void)in_sizes; (void)n_in; (void)out_size;
    const float* x    = (const float*)d_in[0];
    const float* u    = (const float*)d_in[1];
    const float* W    = (const float*)d_in[2];
    const float* c    = (const float*)d_in[3];
    const float* V    = (const float*)d_in[4];
    const float* bvec = (const float*)d_in[5];
    float* out = (float*)d_out;

    cudaFuncSetAttribute(k_scan, cudaFuncAttributeMaxDynamicSharedMemorySize,
                         SMEM_SCAN_BYTES);

    k_pack   <<<D + (D+31)/32, HP>>>(V, c, W);      // launch 0
    k_partial<<<dim3(S-1, B/32), 256>>>(x);          // launch 1
    k_prefix <<<(B*HP)/256, 256>>>();                // launch 2
    k_scan   <<<dim3(S, B/32), TPB, SMEM_SCAN_BYTES>>>(x, u, bvec, out);  // launch 3
}